// round 2
// baseline (speedup 1.0000x reference)
#include <cuda_runtime.h>
#include <cuda_fp16.h>
#include <cstdint>

#define BB 4
#define SS 2048
#define DD 1024
#define HH 16
#define DHK 64
#define DHV 64
#define NN (HH*DHK)   // 1024

// ---------------- scratch (no allocations allowed) ----------------
// input splits (hi/lo fp16)
__device__ __half g_qh[BB*SS*DD];  __device__ __half g_ql[BB*SS*DD];
__device__ __half g_kh[BB*SS*DD];  __device__ __half g_kl[BB*SS*DD];
__device__ __half g_vh[BB*SS*DD];  __device__ __half g_vl[BB*SS*DD];
__device__ __half g_Wqh[DD*NN];    __device__ __half g_Wql[DD*NN];
__device__ __half g_Wkh[DD*NN];    __device__ __half g_Wkl[DD*NN];
__device__ __half g_Wvh[DD*NN];    __device__ __half g_Wvl[DD*NN];
// projected, head-split [B,H,S,64] splits
__device__ __half g_Qh[BB*HH*SS*DHK];  __device__ __half g_Ql[BB*HH*SS*DHK];
__device__ __half g_Kh[BB*HH*SS*DHK];  __device__ __half g_Kl[BB*HH*SS*DHK];
__device__ __half g_Vh[BB*HH*SS*DHV];  __device__ __half g_Vl[BB*HH*SS*DHV];

// ---------------- helpers ----------------
__device__ __forceinline__ uint32_t s2u(const void* p){
    return (uint32_t)__cvta_generic_to_shared(p);
}
__device__ __forceinline__ void ldsm4(uint32_t& r0,uint32_t& r1,uint32_t& r2,uint32_t& r3, uint32_t a){
    asm volatile("ldmatrix.sync.aligned.m8n8.x4.shared.b16 {%0,%1,%2,%3}, [%4];"
        : "=r"(r0),"=r"(r1),"=r"(r2),"=r"(r3) : "r"(a));
}
__device__ __forceinline__ void ldsm4t(uint32_t& r0,uint32_t& r1,uint32_t& r2,uint32_t& r3, uint32_t a){
    asm volatile("ldmatrix.sync.aligned.m8n8.x4.trans.shared.b16 {%0,%1,%2,%3}, [%4];"
        : "=r"(r0),"=r"(r1),"=r"(r2),"=r"(r3) : "r"(a));
}
__device__ __forceinline__ void mma16816(float* c,
        const uint32_t* a, uint32_t b0, uint32_t b1){
    asm volatile("mma.sync.aligned.m16n8k16.row.col.f32.f16.f16.f32 "
        "{%0,%1,%2,%3}, {%4,%5,%6,%7}, {%8,%9}, {%0,%1,%2,%3};"
        : "+f"(c[0]),"+f"(c[1]),"+f"(c[2]),"+f"(c[3])
        : "r"(a[0]),"r"(a[1]),"r"(a[2]),"r"(a[3]),"r"(b0),"r"(b1));
}
__device__ __forceinline__ void cpasync16(uint32_t s, const void* g){
    asm volatile("cp.async.ca.shared.global [%0], [%1], 16;" :: "r"(s), "l"(g));
}
__device__ __forceinline__ uint32_t h2u(__half2 h){
    return *reinterpret_cast<uint32_t*>(&h);
}
__device__ __forceinline__ void split1(float x, __half& h, __half& l){
    h = __float2half_rn(x);
    l = __float2half_rn(x - __half2float(h));
}

// ---------------- fp32 -> fp16 hi/lo split ----------------
__global__ void cvt_split(const float4* __restrict__ src, int n4, int which){
    __half *dh, *dl;
    switch (which){
        case 0: dh=g_qh;  dl=g_ql;  break;
        case 1: dh=g_kh;  dl=g_kl;  break;
        case 2: dh=g_vh;  dl=g_vl;  break;
        case 3: dh=g_Wqh; dl=g_Wql; break;
        case 4: dh=g_Wkh; dl=g_Wkl; break;
        default: dh=g_Wvh; dl=g_Wvl; break;
    }
    int i = blockIdx.x*blockDim.x + threadIdx.x;
    if (i < n4){
        float4 f = src[i];
        __half h0,l0,h1,l1,h2,l2,h3,l3;
        split1(f.x,h0,l0); split1(f.y,h1,l1); split1(f.z,h2,l2); split1(f.w,h3,l3);
        ((__half2*)dh)[2*i+0] = __halves2half2(h0,h1);
        ((__half2*)dh)[2*i+1] = __halves2half2(h2,h3);
        ((__half2*)dl)[2*i+0] = __halves2half2(l0,l1);
        ((__half2*)dl)[2*i+1] = __halves2half2(l2,l3);
    }
}

// ---------------- projection GEMM (split fp16, 3-term) ----------------
// C = (Ah+Al)(Wh+Wl) ~= Ah*Wh + Ah*Wl + Al*Wh ; fp32 accum.
#define PBK 16

__global__ __launch_bounds__(256) void proj_gemm(int which){
    const __half *Ah_, *Al_, *Wh_, *Wl_; __half *Oh, *Ol; float scale;
    if (which==0){ Ah_=g_qh; Al_=g_ql; Wh_=g_Wqh; Wl_=g_Wql; Oh=g_Qh; Ol=g_Ql; scale=0.125f; }
    else if (which==1){ Ah_=g_kh; Al_=g_kl; Wh_=g_Wkh; Wl_=g_Wkl; Oh=g_Kh; Ol=g_Kl; scale=1.f; }
    else { Ah_=g_vh; Al_=g_vl; Wh_=g_Wvh; Wl_=g_Wvl; Oh=g_Vh; Ol=g_Vl; scale=1.f; }

    __shared__ __half Ahs[2][128][24], Als[2][128][24];
    __shared__ __half Whs[2][PBK][136], Wls[2][PBK][136];

    int tid = threadIdx.x;
    int warp = tid >> 5, lane = tid & 31;
    int wm = warp >> 1, wn = warp & 1;     // 4 x 2 warp grid
    int bm0 = blockIdx.y * 128;
    int bn0 = blockIdx.x * 128;

    float acc[2][8][4];
    #pragma unroll
    for (int mi=0;mi<2;mi++)
        #pragma unroll
        for (int nj=0;nj<8;nj++)
            #pragma unroll
            for (int t=0;t<4;t++) acc[mi][nj][t] = 0.f;

    const int KT = DD / PBK;  // 64

    int ar = tid >> 1,  ac = (tid & 1) * 8;
    int wr = tid >> 4,  wc = (tid & 15) * 8;

    // prologue
    {
        cpasync16(s2u(&Ahs[0][ar][ac]), Ah_ + (size_t)(bm0+ar)*DD + ac);
        cpasync16(s2u(&Als[0][ar][ac]), Al_ + (size_t)(bm0+ar)*DD + ac);
        cpasync16(s2u(&Whs[0][wr][wc]), Wh_ + (size_t)wr*NN + bn0 + wc);
        cpasync16(s2u(&Wls[0][wr][wc]), Wl_ + (size_t)wr*NN + bn0 + wc);
        asm volatile("cp.async.commit_group;");
        asm volatile("cp.async.wait_group 0;");
        __syncthreads();
    }

    for (int kt = 0; kt < KT; kt++){
        int buf = kt & 1;
        if (kt + 1 < KT){
            int k0 = (kt+1) * PBK;
            int nb = buf ^ 1;
            cpasync16(s2u(&Ahs[nb][ar][ac]), Ah_ + (size_t)(bm0+ar)*DD + k0 + ac);
            cpasync16(s2u(&Als[nb][ar][ac]), Al_ + (size_t)(bm0+ar)*DD + k0 + ac);
            cpasync16(s2u(&Whs[nb][wr][wc]), Wh_ + (size_t)(k0+wr)*NN + bn0 + wc);
            cpasync16(s2u(&Wls[nb][wr][wc]), Wl_ + (size_t)(k0+wr)*NN + bn0 + wc);
            asm volatile("cp.async.commit_group;");
        }

        uint32_t ah[2][4], al[2][4];
        #pragma unroll
        for (int mi=0; mi<2; mi++){
            ldsm4(ah[mi][0],ah[mi][1],ah[mi][2],ah[mi][3],
                s2u(&Ahs[buf][wm*32 + mi*16 + (lane & 15)][(lane >> 4) << 3]));
            ldsm4(al[mi][0],al[mi][1],al[mi][2],al[mi][3],
                s2u(&Als[buf][wm*32 + mi*16 + (lane & 15)][(lane >> 4) << 3]));
        }
        uint32_t bh[8][2], bl[8][2];
        #pragma unroll
        for (int nj2=0; nj2<4; nj2++){
            uint32_t t0,t1,t2,t3;
            ldsm4t(t0,t1,t2,t3,
                s2u(&Whs[buf][lane & 15][wn*64 + nj2*16 + ((lane >> 4) << 3)]));
            bh[nj2*2][0]=t0; bh[nj2*2][1]=t1; bh[nj2*2+1][0]=t2; bh[nj2*2+1][1]=t3;
            ldsm4t(t0,t1,t2,t3,
                s2u(&Wls[buf][lane & 15][wn*64 + nj2*16 + ((lane >> 4) << 3)]));
            bl[nj2*2][0]=t0; bl[nj2*2][1]=t1; bl[nj2*2+1][0]=t2; bl[nj2*2+1][1]=t3;
        }
        #pragma unroll
        for (int mi=0;mi<2;mi++)
            #pragma unroll
            for (int nj=0;nj<8;nj++){
                mma16816(acc[mi][nj], ah[mi], bh[nj][0], bh[nj][1]);
                mma16816(acc[mi][nj], ah[mi], bl[nj][0], bl[nj][1]);
                mma16816(acc[mi][nj], al[mi], bh[nj][0], bh[nj][1]);
            }

        if (kt + 1 < KT) asm volatile("cp.async.wait_group 0;");
        __syncthreads();
    }

    // epilogue: split + scatter into [B,H,S,64]
    int r0 = lane >> 2, c0 = (lane & 3) * 2;
    #pragma unroll
    for (int mi=0;mi<2;mi++){
        #pragma unroll
        for (int ri=0;ri<2;ri++){
            int m = bm0 + wm*32 + mi*16 + r0 + ri*8;
            int bbi = m >> 11, s = m & (SS-1);
            #pragma unroll
            for (int nj=0;nj<8;nj++){
                int n = bn0 + wn*64 + nj*8 + c0;
                int h = n >> 6, c = n & 63;
                float x0 = acc[mi][nj][ri*2+0]*scale;
                float x1 = acc[mi][nj][ri*2+1]*scale;
                __half h0,l0,h1,l1;
                split1(x0,h0,l0); split1(x1,h1,l1);
                size_t base = (((size_t)(bbi*HH + h)*SS + s) << 6) + c;
                *(__half2*)&Oh[base] = __halves2half2(h0,h1);
                *(__half2*)&Ol[base] = __halves2half2(l0,l1);
            }
        }
    }
}

// ---------------- flash attention (split fp16, tie-exact masking) ----------------
// 64 q-rows per block, 4 warps; 32-key blocks; causal skipping + future-phase
// vote for rows whose entire visible range is v_masked (reference -1e9 ties).
__global__ __launch_bounds__(128) void attn_kernel(const float* __restrict__ v_mask,
                                                   const float* __restrict__ q_mask,
                                                   float* __restrict__ out){
    int qt = blockIdx.x, h = blockIdx.y, b = blockIdx.z;
    int tid = threadIdx.x, warp = tid >> 5, lane = tid & 31;
    int qb = qt * 64;

    __shared__ __half Qhs[64][72], Qls[64][72];
    __shared__ __half Khs[32][72], Kls[32][72];
    __shared__ __half Vhs[32][72], Vls[32][72];
    __shared__ float vmadd[32];

    size_t hb = (size_t)(b*HH + h) * SS;
    const __half* Qph = g_Qh + hb*DHK;  const __half* Qpl = g_Ql + hb*DHK;
    const __half* Kph = g_Kh + hb*DHK;  const __half* Kpl = g_Kl + hb*DHK;
    const __half* Vph = g_Vh + hb*DHV;  const __half* Vpl = g_Vl + hb*DHV;

    // stage Q tile once
    for (int c = tid; c < 512; c += 128){
        int r = c >> 3, cc = (c & 7) * 8;
        *(uint4*)&Qhs[r][cc] = *(const uint4*)&Qph[(size_t)(qb + r)*DHK + cc];
        *(uint4*)&Qls[r][cc] = *(const uint4*)&Qpl[(size_t)(qb + r)*DHK + cc];
    }
    __syncthreads();

    uint32_t qh[4][4], ql[4][4];
    #pragma unroll
    for (int kk=0; kk<4; kk++){
        ldsm4(qh[kk][0],qh[kk][1],qh[kk][2],qh[kk][3],
            s2u(&Qhs[warp*16 + (lane & 15)][kk*16 + ((lane >> 4) << 3)]));
        ldsm4(ql[kk][0],ql[kk][1],ql[kk][2],ql[kk][3],
            s2u(&Qls[warp*16 + (lane & 15)][kk*16 + ((lane >> 4) << 3)]));
    }

    float m_r[2] = {-1e30f, -1e30f};
    float l_r[2] = {0.f, 0.f};
    float o[8][4];
    #pragma unroll
    for (int dj=0;dj<8;dj++)
        #pragma unroll
        for (int t=0;t<4;t++) o[dj][t] = 0.f;

    int r0 = lane >> 2, c0 = (lane & 3) * 2;
    int qrow0 = qb + warp*16 + r0;

    int kb = 0;
    bool future = false;
    for (;;){
        if (!future && kb > qb + 32){
            // any row with its entire visible range v_masked? (m == -1e9 exactly)
            int need = __syncthreads_or((m_r[0] < -5e8f) || (m_r[1] < -5e8f));
            if (!need) break;
            future = true;
        }
        if (kb >= SS) break;

        __syncthreads();
        if (!future){
            for (int c = tid; c < 256; c += 128){
                int r = c >> 3, cc = (c & 7) * 8;
                *(uint4*)&Khs[r][cc] = *(const uint4*)&Kph[(size_t)(kb + r)*DHK + cc];
                *(uint4*)&Kls[r][cc] = *(const uint4*)&Kpl[(size_t)(kb + r)*DHK + cc];
            }
        }
        for (int c = tid; c < 256; c += 128){
            int r = c >> 3, cc = (c & 7) * 8;
            *(uint4*)&Vhs[r][cc] = *(const uint4*)&Vph[(size_t)(kb + r)*DHV + cc];
            *(uint4*)&Vls[r][cc] = *(const uint4*)&Vpl[(size_t)(kb + r)*DHV + cc];
        }
        if (tid < 32) vmadd[tid] = (1.0f - v_mask[b*SS + kb + tid]) * -1e9f;
        __syncthreads();

        // ---- scores ----
        float sc[4][4];
        #pragma unroll
        for (int nj=0;nj<4;nj++)
            #pragma unroll
            for (int t=0;t<4;t++) sc[nj][t] = 0.f;

        if (!future){
            #pragma unroll
            for (int kk=0;kk<4;kk++){
                uint32_t bh[4][2], bl[4][2];
                int g = lane >> 3;
                #pragma unroll
                for (int nj2=0;nj2<2;nj2++){
                    uint32_t t0,t1,t2,t3;
                    uint32_t addr_r = nj2*16 + ((g>>1)<<3) + (lane & 7);
                    uint32_t addr_c = kk*16 + ((g & 1)<<3);
                    ldsm4(t0,t1,t2,t3, s2u(&Khs[addr_r][addr_c]));
                    bh[nj2*2][0]=t0; bh[nj2*2][1]=t1; bh[nj2*2+1][0]=t2; bh[nj2*2+1][1]=t3;
                    ldsm4(t0,t1,t2,t3, s2u(&Kls[addr_r][addr_c]));
                    bl[nj2*2][0]=t0; bl[nj2*2][1]=t1; bl[nj2*2+1][0]=t2; bl[nj2*2+1][1]=t3;
                }
                #pragma unroll
                for (int nj=0;nj<4;nj++){
                    mma16816(sc[nj], qh[kk], bh[nj][0], bh[nj][1]);
                    mma16816(sc[nj], qh[kk], bl[nj][0], bl[nj][1]);
                    mma16816(sc[nj], ql[kk], bh[nj][0], bh[nj][1]);
                }
            }
        }

        // ---- mask + online softmax ----
        bool diagchk = (kb + 31 > qb) && !future;
        #pragma unroll
        for (int ri=0;ri<2;ri++){
            int qrow = qrow0 + ri*8;
            float mx = -1e30f;
            #pragma unroll
            for (int nj=0;nj<4;nj++){
                #pragma unroll
                for (int i=0;i<2;i++){
                    int kc = nj*8 + c0 + i;
                    float sv;
                    if (future){
                        sv = vmadd[kc] - 1e9f;     // score rounds away at -1e9 ulp
                    } else {
                        sv = sc[nj][ri*2+i] + vmadd[kc];
                        if (diagchk && (kb + kc > qrow)) sv -= 1e9f;
                    }
                    sc[nj][ri*2+i] = sv;
                    mx = fmaxf(mx, sv);
                }
            }
            mx = fmaxf(mx, __shfl_xor_sync(0xffffffffu, mx, 1));
            mx = fmaxf(mx, __shfl_xor_sync(0xffffffffu, mx, 2));
            float mnew = fmaxf(m_r[ri], mx);
            float alpha = __expf(m_r[ri] - mnew);
            float rowsum = 0.f;
            #pragma unroll
            for (int nj=0;nj<4;nj++){
                #pragma unroll
                for (int i=0;i<2;i++){
                    float p = __expf(sc[nj][ri*2+i] - mnew);
                    sc[nj][ri*2+i] = p;
                    rowsum += p;
                }
            }
            rowsum += __shfl_xor_sync(0xffffffffu, rowsum, 1);
            rowsum += __shfl_xor_sync(0xffffffffu, rowsum, 2);
            l_r[ri] = l_r[ri]*alpha + rowsum;
            m_r[ri] = mnew;
            #pragma unroll
            for (int dj=0;dj<8;dj++){
                o[dj][ri*2+0] *= alpha;
                o[dj][ri*2+1] *= alpha;
            }
        }

        // ---- P split to hi/lo fp16 ----
        uint32_t ph[2][4], pl[2][4];
        #pragma unroll
        for (int kk2=0;kk2<2;kk2++){
            #pragma unroll
            for (int q4=0;q4<4;q4++){
                int njs = kk2*2 + (q4 >> 1);
                int e0 = (q4 & 1) * 2;
                float p0 = sc[njs][e0+0], p1 = sc[njs][e0+1];
                __half h0,l0,h1,l1;
                split1(p0,h0,l0); split1(p1,h1,l1);
                ph[kk2][q4] = h2u(__halves2half2(h0,h1));
                pl[kk2][q4] = h2u(__halves2half2(l0,l1));
            }
        }
        // reorder to A-fragment order: a0=(r,k0),a1=(r+8,k0),a2=(r,k8),a3=(r+8,k8)
        // built above as: q4=0 ->(r,k0..)? mapping: njs = kk2*2 + q4/2 covers k-chunks,
        // e0 selects row group. Rebuild explicitly:
        uint32_t pah[2][4], pal[2][4];
        #pragma unroll
        for (int kk2=0;kk2<2;kk2++){
            // sc[kk2*2+0][0,1] = (r, k 0..7); [2,3] = (r+8, k 0..7)
            // sc[kk2*2+1][0,1] = (r, k 8..15); [2,3] = (r+8, k 8..15)
            pah[kk2][0] = ph[kk2][0]; pal[kk2][0] = pl[kk2][0];
            pah[kk2][1] = ph[kk2][1]; pal[kk2][1] = pl[kk2][1];
            pah[kk2][2] = ph[kk2][2]; pal[kk2][2] = pl[kk2][2];
            pah[kk2][3] = ph[kk2][3]; pal[kk2][3] = pl[kk2][3];
        }
        // NOTE: ph[kk2][q4] with njs=kk2*2+q4/2, e0=(q4&1)*2:
        //   q4=0: (nj=kk2*2,   elems 0,1) = (r,   k0..7)  -> a0  OK
        //   q4=1: (nj=kk2*2,   elems 2,3) = (r+8, k0..7)  -> a1  OK
        //   q4=2: (nj=kk2*2+1, elems 0,1) = (r,   k8..15) -> a2  OK
        //   q4=3: (nj=kk2*2+1, elems 2,3) = (r+8, k8..15) -> a3  OK

        // ---- O += P V (3-term) ----
        #pragma unroll
        for (int kk2=0;kk2<2;kk2++){
            uint32_t vh[8][2], vl[8][2];
            #pragma unroll
            for (int dj2=0;dj2<4;dj2++){
                uint32_t t0,t1,t2,t3;
                uint32_t addr_r = kk2*16 + (lane & 15);
                uint32_t addr_c = dj2*16 + ((lane >> 4) << 3);
                ldsm4t(t0,t1,t2,t3, s2u(&Vhs[addr_r][addr_c]));
                vh[dj2*2][0]=t0; vh[dj2*2][1]=t1; vh[dj2*2+1][0]=t2; vh[dj2*2+1][1]=t3;
                ldsm4t(t0,t1,t2,t3, s2u(&Vls[addr_r][addr_c]));
                vl[dj2*2][0]=t0; vl[dj2*2][1]=t1; vl[dj2*2+1][0]=t2; vl[dj2*2+1][1]=t3;
            }
            #pragma unroll
            for (int dj=0;dj<8;dj++){
                mma16816(o[dj], pah[kk2], vh[dj][0], vh[dj][1]);
                mma16816(o[dj], pah[kk2], vl[dj][0], vl[dj][1]);
                mma16816(o[dj], pal[kk2], vh[dj][0], vh[dj][1]);
            }
        }
        kb += 32;
    }

    // ---- finalize ----
    #pragma unroll
    for (int ri=0;ri<2;ri++){
        int qrow = qrow0 + ri*8;
        float qm = q_mask[b*SS + qrow];
        float inv = qm / l_r[ri];
        #pragma unroll
        for (int dj=0;dj<8;dj++){
            float2 v2;
            v2.x = o[dj][ri*2+0] * inv;
            v2.y = o[dj][ri*2+1] * inv;
            *(float2*)&out[(size_t)(b*SS + qrow)*(HH*DHV) + h*DHV + dj*8 + c0] = v2;
        }
    }
}

// ---------------- launch ----------------
extern "C" void kernel_launch(void* const* d_in, const int* in_sizes, int n_in,
                              void* d_out, int out_size){
    const float* q      = (const float*)d_in[0];
    const float* k      = (const float*)d_in[1];
    const float* v      = (const float*)d_in[2];
    const float* v_mask = (const float*)d_in[3];
    const float* q_mask = (const float*)d_in[4];
    const float* Wq     = (const float*)d_in[5];
    const float* Wk     = (const float*)d_in[6];
    const float* Wv     = (const float*)d_in[7];
    float* out = (float*)d_out;

    int n4x = BB*SS*DD/4;   // 2,097,152
    int n4w = DD*NN/4;      //   262,144
    cvt_split<<<(n4x+255)/256, 256>>>((const float4*)q,  n4x, 0);
    cvt_split<<<(n4x+255)/256, 256>>>((const float4*)k,  n4x, 1);
    cvt_split<<<(n4x+255)/256, 256>>>((const float4*)v,  n4x, 2);
    cvt_split<<<(n4w+255)/256, 256>>>((const float4*)Wq, n4w, 3);
    cvt_split<<<(n4w+255)/256, 256>>>((const float4*)Wk, n4w, 4);
    cvt_split<<<(n4w+255)/256, 256>>>((const float4*)Wv, n4w, 5);

    dim3 ggrid(NN/128, (BB*SS)/128);   // (8, 64)
    proj_gemm<<<ggrid, 256>>>(0);
    proj_gemm<<<ggrid, 256>>>(1);
    proj_gemm<<<ggrid, 256>>>(2);

    attn_kernel<<<dim3(SS/64, HH, BB), 128>>>(v_mask, q_mask, out);
}

// round 3
// speedup vs baseline: 1.3339x; 1.3339x over previous
#include <cuda_runtime.h>
#include <cuda_fp16.h>
#include <cstdint>

#define BB 4
#define SS 2048
#define DD 1024
#define HH 16
#define DHK 64
#define DHV 64
#define NN (HH*DHK)   // 1024

// ---------------- scratch (no allocations allowed) ----------------
__device__ __half g_qh[BB*SS*DD];  __device__ __half g_ql[BB*SS*DD];
__device__ __half g_kh[BB*SS*DD];  __device__ __half g_kl[BB*SS*DD];
__device__ __half g_vh[BB*SS*DD];  __device__ __half g_vl[BB*SS*DD];
__device__ __half g_Wqh[DD*NN];    __device__ __half g_Wql[DD*NN];
__device__ __half g_Wkh[DD*NN];    __device__ __half g_Wkl[DD*NN];
__device__ __half g_Wvh[DD*NN];    __device__ __half g_Wvl[DD*NN];
__device__ __half g_Qh[BB*HH*SS*DHK];  __device__ __half g_Ql[BB*HH*SS*DHK];
__device__ __half g_Kh[BB*HH*SS*DHK];  __device__ __half g_Kl[BB*HH*SS*DHK];
__device__ __half g_Vh[BB*HH*SS*DHV];  __device__ __half g_Vl[BB*HH*SS*DHV];

// ---------------- helpers ----------------
__device__ __forceinline__ uint32_t s2u(const void* p){
    return (uint32_t)__cvta_generic_to_shared(p);
}
__device__ __forceinline__ void ldsm4(uint32_t& r0,uint32_t& r1,uint32_t& r2,uint32_t& r3, uint32_t a){
    asm volatile("ldmatrix.sync.aligned.m8n8.x4.shared.b16 {%0,%1,%2,%3}, [%4];"
        : "=r"(r0),"=r"(r1),"=r"(r2),"=r"(r3) : "r"(a));
}
__device__ __forceinline__ void ldsm4t(uint32_t& r0,uint32_t& r1,uint32_t& r2,uint32_t& r3, uint32_t a){
    asm volatile("ldmatrix.sync.aligned.m8n8.x4.trans.shared.b16 {%0,%1,%2,%3}, [%4];"
        : "=r"(r0),"=r"(r1),"=r"(r2),"=r"(r3) : "r"(a));
}
__device__ __forceinline__ void mma16816(float* c, const uint32_t* a, uint32_t b0, uint32_t b1){
    asm volatile("mma.sync.aligned.m16n8k16.row.col.f32.f16.f16.f32 "
        "{%0,%1,%2,%3}, {%4,%5,%6,%7}, {%8,%9}, {%0,%1,%2,%3};"
        : "+f"(c[0]),"+f"(c[1]),"+f"(c[2]),"+f"(c[3])
        : "r"(a[0]),"r"(a[1]),"r"(a[2]),"r"(a[3]),"r"(b0),"r"(b1));
}
__device__ __forceinline__ void cpasync16(uint32_t s, const void* g){
    asm volatile("cp.async.ca.shared.global [%0], [%1], 16;" :: "r"(s), "l"(g));
}
__device__ __forceinline__ void cpasync4(uint32_t s, const void* g){
    asm volatile("cp.async.ca.shared.global [%0], [%1], 4;" :: "r"(s), "l"(g));
}
#define CP_COMMIT() asm volatile("cp.async.commit_group;")
#define CP_WAIT0()  asm volatile("cp.async.wait_group 0;")
__device__ __forceinline__ uint32_t h2u(__half2 h){
    return *reinterpret_cast<uint32_t*>(&h);
}
__device__ __forceinline__ void split1(float x, __half& h, __half& l){
    h = __float2half_rn(x);
    l = __float2half_rn(x - __half2float(h));
}

// ---------------- fp32 -> fp16 hi/lo split (merged launches) ----------------
__global__ void cvtX(const float4* __restrict__ q, const float4* __restrict__ k,
                     const float4* __restrict__ v){
    const int n4 = BB*SS*DD/4;
    int i = blockIdx.x*blockDim.x + threadIdx.x;
    const float4* src; __half *dh, *dl; int j;
    if (i < n4){ src=q; dh=g_qh; dl=g_ql; j=i; }
    else if (i < 2*n4){ src=k; dh=g_kh; dl=g_kl; j=i-n4; }
    else if (i < 3*n4){ src=v; dh=g_vh; dl=g_vl; j=i-2*n4; }
    else return;
    float4 f = src[j];
    __half h0,l0,h1,l1,h2,l2,h3,l3;
    split1(f.x,h0,l0); split1(f.y,h1,l1); split1(f.z,h2,l2); split1(f.w,h3,l3);
    ((__half2*)dh)[2*j+0] = __halves2half2(h0,h1);
    ((__half2*)dh)[2*j+1] = __halves2half2(h2,h3);
    ((__half2*)dl)[2*j+0] = __halves2half2(l0,l1);
    ((__half2*)dl)[2*j+1] = __halves2half2(l2,l3);
}
__global__ void cvtW(const float4* __restrict__ wq, const float4* __restrict__ wk,
                     const float4* __restrict__ wv){
    const int n4 = DD*NN/4;
    int i = blockIdx.x*blockDim.x + threadIdx.x;
    const float4* src; __half *dh, *dl; int j;
    if (i < n4){ src=wq; dh=g_Wqh; dl=g_Wql; j=i; }
    else if (i < 2*n4){ src=wk; dh=g_Wkh; dl=g_Wkl; j=i-n4; }
    else if (i < 3*n4){ src=wv; dh=g_Wvh; dl=g_Wvl; j=i-2*n4; }
    else return;
    float4 f = src[j];
    __half h0,l0,h1,l1,h2,l2,h3,l3;
    split1(f.x,h0,l0); split1(f.y,h1,l1); split1(f.z,h2,l2); split1(f.w,h3,l3);
    ((__half2*)dh)[2*j+0] = __halves2half2(h0,h1);
    ((__half2*)dh)[2*j+1] = __halves2half2(h2,h3);
    ((__half2*)dl)[2*j+0] = __halves2half2(l0,l1);
    ((__half2*)dl)[2*j+1] = __halves2half2(l2,l3);
}

// ---------------- projection GEMM (split fp16, 3-term, BK=32) ----------------
#define PBK 32

struct ProjSmem {
    __half Ah[2][128][40], Al[2][128][40];
    __half Wh[2][PBK][136], Wl[2][PBK][136];
};

__global__ __launch_bounds__(256) void proj_gemm(int which){
    const __half *Ah_, *Al_, *Wh_, *Wl_; __half *Oh, *Ol; float scale;
    if (which==0){ Ah_=g_qh; Al_=g_ql; Wh_=g_Wqh; Wl_=g_Wql; Oh=g_Qh; Ol=g_Ql; scale=0.125f; }
    else if (which==1){ Ah_=g_kh; Al_=g_kl; Wh_=g_Wkh; Wl_=g_Wkl; Oh=g_Kh; Ol=g_Kl; scale=1.f; }
    else { Ah_=g_vh; Al_=g_vl; Wh_=g_Wvh; Wl_=g_Wvl; Oh=g_Vh; Ol=g_Vl; scale=1.f; }

    extern __shared__ char smem_raw[];
    ProjSmem& sm = *reinterpret_cast<ProjSmem*>(smem_raw);

    int tid = threadIdx.x;
    int warp = tid >> 5, lane = tid & 31;
    int wm = warp >> 1, wn = warp & 1;     // 4 x 2 warp grid
    int bm0 = blockIdx.y * 128;
    int bn0 = blockIdx.x * 128;

    float acc[2][8][4];
    #pragma unroll
    for (int mi=0;mi<2;mi++)
        #pragma unroll
        for (int nj=0;nj<8;nj++)
            #pragma unroll
            for (int t=0;t<4;t++) acc[mi][nj][t] = 0.f;

    const int KT = DD / PBK;  // 32

    // prologue: stage tile 0
    #pragma unroll
    for (int j=0;j<2;j++){
        int idx = tid + j*256;
        int r = idx >> 2, cc = (idx & 3) * 8;
        cpasync16(s2u(&sm.Ah[0][r][cc]), Ah_ + (size_t)(bm0+r)*DD + cc);
        cpasync16(s2u(&sm.Al[0][r][cc]), Al_ + (size_t)(bm0+r)*DD + cc);
        int wr = idx >> 4, wc = (idx & 15) * 8;
        cpasync16(s2u(&sm.Wh[0][wr][wc]), Wh_ + (size_t)wr*NN + bn0 + wc);
        cpasync16(s2u(&sm.Wl[0][wr][wc]), Wl_ + (size_t)wr*NN + bn0 + wc);
    }
    CP_COMMIT(); CP_WAIT0();
    __syncthreads();

    for (int kt = 0; kt < KT; kt++){
        int buf = kt & 1;
        if (kt + 1 < KT){
            int k0 = (kt+1) * PBK;
            int nb = buf ^ 1;
            #pragma unroll
            for (int j=0;j<2;j++){
                int idx = tid + j*256;
                int r = idx >> 2, cc = (idx & 3) * 8;
                cpasync16(s2u(&sm.Ah[nb][r][cc]), Ah_ + (size_t)(bm0+r)*DD + k0 + cc);
                cpasync16(s2u(&sm.Al[nb][r][cc]), Al_ + (size_t)(bm0+r)*DD + k0 + cc);
                int wr = idx >> 4, wc = (idx & 15) * 8;
                cpasync16(s2u(&sm.Wh[nb][wr][wc]), Wh_ + (size_t)(k0+wr)*NN + bn0 + wc);
                cpasync16(s2u(&sm.Wl[nb][wr][wc]), Wl_ + (size_t)(k0+wr)*NN + bn0 + wc);
            }
            CP_COMMIT();
        }

        #pragma unroll
        for (int kk=0; kk<2; kk++){
            int k0c = kk*16;
            uint32_t ah[2][4], al[2][4];
            #pragma unroll
            for (int mi=0; mi<2; mi++){
                ldsm4(ah[mi][0],ah[mi][1],ah[mi][2],ah[mi][3],
                    s2u(&sm.Ah[buf][wm*32 + mi*16 + (lane & 15)][k0c + ((lane >> 4) << 3)]));
                ldsm4(al[mi][0],al[mi][1],al[mi][2],al[mi][3],
                    s2u(&sm.Al[buf][wm*32 + mi*16 + (lane & 15)][k0c + ((lane >> 4) << 3)]));
            }
            uint32_t bh[8][2], bl[8][2];
            #pragma unroll
            for (int nj2=0; nj2<4; nj2++){
                uint32_t t0,t1,t2,t3;
                ldsm4t(t0,t1,t2,t3,
                    s2u(&sm.Wh[buf][k0c + (lane & 15)][wn*64 + nj2*16 + ((lane >> 4) << 3)]));
                bh[nj2*2][0]=t0; bh[nj2*2][1]=t1; bh[nj2*2+1][0]=t2; bh[nj2*2+1][1]=t3;
                ldsm4t(t0,t1,t2,t3,
                    s2u(&sm.Wl[buf][k0c + (lane & 15)][wn*64 + nj2*16 + ((lane >> 4) << 3)]));
                bl[nj2*2][0]=t0; bl[nj2*2][1]=t1; bl[nj2*2+1][0]=t2; bl[nj2*2+1][1]=t3;
            }
            #pragma unroll
            for (int mi=0;mi<2;mi++)
                #pragma unroll
                for (int nj=0;nj<8;nj++){
                    mma16816(acc[mi][nj], ah[mi], bh[nj][0], bh[nj][1]);
                    mma16816(acc[mi][nj], ah[mi], bl[nj][0], bl[nj][1]);
                    mma16816(acc[mi][nj], al[mi], bh[nj][0], bh[nj][1]);
                }
        }

        if (kt + 1 < KT) CP_WAIT0();
        __syncthreads();
    }

    // epilogue: split + scatter into [B,H,S,64]
    int r0 = lane >> 2, c0 = (lane & 3) * 2;
    #pragma unroll
    for (int mi=0;mi<2;mi++){
        #pragma unroll
        for (int ri=0;ri<2;ri++){
            int m = bm0 + wm*32 + mi*16 + r0 + ri*8;
            int bbi = m >> 11, s = m & (SS-1);
            #pragma unroll
            for (int nj=0;nj<8;nj++){
                int n = bn0 + wn*64 + nj*8 + c0;
                int h = n >> 6, c = n & 63;
                float x0 = acc[mi][nj][ri*2+0]*scale;
                float x1 = acc[mi][nj][ri*2+1]*scale;
                __half h0,l0,h1,l1;
                split1(x0,h0,l0); split1(x1,h1,l1);
                size_t base = (((size_t)(bbi*HH + h)*SS + s) << 6) + c;
                *(__half2*)&Oh[base] = __halves2half2(h0,h1);
                *(__half2*)&Ol[base] = __halves2half2(l0,l1);
            }
        }
    }
}

// ---------------- flash attention (split fp16, 64-key blocks, double-buffered) ----------------
struct AttnSmem {
    __half Qh[64][72], Ql[64][72];
    __half Kh[2][64][72], Kl[2][64][72];
    __half Vh[2][64][72], Vl[2][64][72];
    float  vmraw[2][64];
};

__global__ __launch_bounds__(128) void attn_kernel(const float* __restrict__ v_mask,
                                                   const float* __restrict__ q_mask,
                                                   float* __restrict__ out){
    int qt = blockIdx.x, h = blockIdx.y, b = blockIdx.z;
    int tid = threadIdx.x, warp = tid >> 5, lane = tid & 31;
    int qb = qt * 64;

    extern __shared__ char smem_raw[];
    AttnSmem& sm = *reinterpret_cast<AttnSmem*>(smem_raw);

    size_t hb = (size_t)(b*HH + h) * SS;
    const __half* Qph = g_Qh + hb*DHK;  const __half* Qpl = g_Ql + hb*DHK;
    const __half* Kph = g_Kh + hb*DHK;  const __half* Kpl = g_Kl + hb*DHK;
    const __half* Vph = g_Vh + hb*DHV;  const __half* Vpl = g_Vl + hb*DHV;
    const float*  vmp = v_mask + b*SS;

    // prologue: async-stage K/V block 0, plain-stage Q
    for (int c = tid; c < 512; c += 128){
        int r = c >> 3, cc = (c & 7) * 8;
        size_t off = (size_t)r*DHK + cc;
        cpasync16(s2u(&sm.Kh[0][r][cc]), Kph + off);
        cpasync16(s2u(&sm.Kl[0][r][cc]), Kpl + off);
        cpasync16(s2u(&sm.Vh[0][r][cc]), Vph + off);
        cpasync16(s2u(&sm.Vl[0][r][cc]), Vpl + off);
    }
    if (tid < 64) cpasync4(s2u(&sm.vmraw[0][tid]), vmp + tid);
    CP_COMMIT();
    for (int c = tid; c < 512; c += 128){
        int r = c >> 3, cc = (c & 7) * 8;
        *(uint4*)&sm.Qh[r][cc] = *(const uint4*)&Qph[(size_t)(qb + r)*DHK + cc];
        *(uint4*)&sm.Ql[r][cc] = *(const uint4*)&Qpl[(size_t)(qb + r)*DHK + cc];
    }
    CP_WAIT0();
    __syncthreads();

    uint32_t qh[4][4], ql[4][4];
    #pragma unroll
    for (int kk=0; kk<4; kk++){
        ldsm4(qh[kk][0],qh[kk][1],qh[kk][2],qh[kk][3],
            s2u(&sm.Qh[warp*16 + (lane & 15)][kk*16 + ((lane >> 4) << 3)]));
        ldsm4(ql[kk][0],ql[kk][1],ql[kk][2],ql[kk][3],
            s2u(&sm.Ql[warp*16 + (lane & 15)][kk*16 + ((lane >> 4) << 3)]));
    }

    float m_r[2] = {-1e30f, -1e30f};
    float l_r[2] = {0.f, 0.f};
    float o[8][4];
    #pragma unroll
    for (int dj=0;dj<8;dj++)
        #pragma unroll
        for (int t=0;t<4;t++) o[dj][t] = 0.f;

    int r0 = lane >> 2, c0 = (lane & 3) * 2;
    int qrow0 = qb + warp*16 + r0;
    int g = lane >> 3;

    const int nvis = qt + 1;  // visible 64-key blocks

    for (int ib = 0; ib < nvis; ib++){
        int buf = ib & 1;
        int kb = ib * 64;
        bool more = (ib + 1 < nvis);
        if (more){
            int nb = buf ^ 1;
            int kb2 = kb + 64;
            for (int c = tid; c < 512; c += 128){
                int r = c >> 3, cc = (c & 7) * 8;
                size_t off = (size_t)(kb2 + r)*DHK + cc;
                cpasync16(s2u(&sm.Kh[nb][r][cc]), Kph + off);
                cpasync16(s2u(&sm.Kl[nb][r][cc]), Kpl + off);
                cpasync16(s2u(&sm.Vh[nb][r][cc]), Vph + off);
                cpasync16(s2u(&sm.Vl[nb][r][cc]), Vpl + off);
            }
            if (tid < 64) cpasync4(s2u(&sm.vmraw[nb][tid]), vmp + kb2 + tid);
            CP_COMMIT();
        }

        // ---- scores: S = Q K^T (3-term split) ----
        float sc[8][4];
        #pragma unroll
        for (int nj=0;nj<8;nj++)
            #pragma unroll
            for (int t=0;t<4;t++) sc[nj][t] = 0.f;

        #pragma unroll
        for (int kk=0;kk<4;kk++){
            uint32_t bh[8][2], bl[8][2];
            #pragma unroll
            for (int nj2=0;nj2<4;nj2++){
                uint32_t t0,t1,t2,t3;
                int ar = nj2*16 + ((g>>1)<<3) + (lane & 7);
                int ac = kk*16 + ((g & 1)<<3);
                ldsm4(t0,t1,t2,t3, s2u(&sm.Kh[buf][ar][ac]));
                bh[nj2*2][0]=t0; bh[nj2*2][1]=t1; bh[nj2*2+1][0]=t2; bh[nj2*2+1][1]=t3;
                ldsm4(t0,t1,t2,t3, s2u(&sm.Kl[buf][ar][ac]));
                bl[nj2*2][0]=t0; bl[nj2*2][1]=t1; bl[nj2*2+1][0]=t2; bl[nj2*2+1][1]=t3;
            }
            #pragma unroll
            for (int nj=0;nj<8;nj++){
                mma16816(sc[nj], qh[kk], bh[nj][0], bh[nj][1]);
                mma16816(sc[nj], qh[kk], bl[nj][0], bl[nj][1]);
                mma16816(sc[nj], ql[kk], bh[nj][0], bh[nj][1]);
            }
        }

        // ---- mask + online softmax ----
        bool diag = (kb == qb);
        #pragma unroll
        for (int ri=0;ri<2;ri++){
            int qrow = qrow0 + ri*8;
            float mx = -1e30f;
            #pragma unroll
            for (int nj=0;nj<8;nj++){
                #pragma unroll
                for (int i=0;i<2;i++){
                    int kc = nj*8 + c0 + i;
                    float vm = sm.vmraw[buf][kc];
                    float sv = sc[nj][ri*2+i] - (1.0f - vm)*1e9f;
                    if (diag && (kb + kc > qrow)) sv -= 1e9f;
                    sc[nj][ri*2+i] = sv;
                    mx = fmaxf(mx, sv);
                }
            }
            mx = fmaxf(mx, __shfl_xor_sync(0xffffffffu, mx, 1));
            mx = fmaxf(mx, __shfl_xor_sync(0xffffffffu, mx, 2));
            float mnew = fmaxf(m_r[ri], mx);
            float alpha = __expf(m_r[ri] - mnew);
            float rowsum = 0.f;
            #pragma unroll
            for (int nj=0;nj<8;nj++){
                #pragma unroll
                for (int i=0;i<2;i++){
                    float p = __expf(sc[nj][ri*2+i] - mnew);
                    sc[nj][ri*2+i] = p;
                    rowsum += p;
                }
            }
            rowsum += __shfl_xor_sync(0xffffffffu, rowsum, 1);
            rowsum += __shfl_xor_sync(0xffffffffu, rowsum, 2);
            l_r[ri] = l_r[ri]*alpha + rowsum;
            m_r[ri] = mnew;
            #pragma unroll
            for (int dj=0;dj<8;dj++){
                o[dj][ri*2+0] *= alpha;
                o[dj][ri*2+1] *= alpha;
            }
        }

        // ---- P split to hi/lo fp16 fragments ----
        uint32_t pah[4][4], pal[4][4];
        #pragma unroll
        for (int kk2=0;kk2<4;kk2++){
            int e = kk2*2;
            __half h0,l0,h1,l1;
            split1(sc[e][0],h0,l0); split1(sc[e][1],h1,l1);
            pah[kk2][0] = h2u(__halves2half2(h0,h1)); pal[kk2][0] = h2u(__halves2half2(l0,l1));
            split1(sc[e][2],h0,l0); split1(sc[e][3],h1,l1);
            pah[kk2][1] = h2u(__halves2half2(h0,h1)); pal[kk2][1] = h2u(__halves2half2(l0,l1));
            split1(sc[e+1][0],h0,l0); split1(sc[e+1][1],h1,l1);
            pah[kk2][2] = h2u(__halves2half2(h0,h1)); pal[kk2][2] = h2u(__halves2half2(l0,l1));
            split1(sc[e+1][2],h0,l0); split1(sc[e+1][3],h1,l1);
            pah[kk2][3] = h2u(__halves2half2(h0,h1)); pal[kk2][3] = h2u(__halves2half2(l0,l1));
        }

        // ---- O += P V (3-term) ----
        #pragma unroll
        for (int kk2=0;kk2<4;kk2++){
            uint32_t vh[8][2], vl[8][2];
            #pragma unroll
            for (int dj2=0;dj2<4;dj2++){
                uint32_t t0,t1,t2,t3;
                int ar = kk2*16 + (lane & 15);
                int ac = dj2*16 + ((lane >> 4) << 3);
                ldsm4t(t0,t1,t2,t3, s2u(&sm.Vh[buf][ar][ac]));
                vh[dj2*2][0]=t0; vh[dj2*2][1]=t1; vh[dj2*2+1][0]=t2; vh[dj2*2+1][1]=t3;
                ldsm4t(t0,t1,t2,t3, s2u(&sm.Vl[buf][ar][ac]));
                vl[dj2*2][0]=t0; vl[dj2*2][1]=t1; vl[dj2*2+1][0]=t2; vl[dj2*2+1][1]=t3;
            }
            #pragma unroll
            for (int dj=0;dj<8;dj++){
                mma16816(o[dj], pah[kk2], vh[dj][0], vh[dj][1]);
                mma16816(o[dj], pah[kk2], vl[dj][0], vl[dj][1]);
                mma16816(o[dj], pal[kk2], vh[dj][0], vh[dj][1]);
            }
        }

        if (more) CP_WAIT0();
        __syncthreads();
    }

    // ---- future phase: rows whose entire visible range was v_masked ----
    // Reference: s - 1e9 rounds to exactly -1e9 for |s|<32, so a fully-masked-visible
    // row ties uniformly with all future non-vmasked keys. Reproduce exactly.
    int need = __syncthreads_or((m_r[0] < -5e8f) || (m_r[1] < -5e8f));
    if (need){
        for (int kb = qb + 64; kb < SS; kb += 64){
            __syncthreads();
            for (int c = tid; c < 512; c += 128){
                int r = c >> 3, cc = (c & 7) * 8;
                size_t off = (size_t)(kb + r)*DHV + cc;
                *(uint4*)&sm.Vh[0][r][cc] = *(const uint4*)&Vph[off];
                *(uint4*)&sm.Vl[0][r][cc] = *(const uint4*)&Vpl[off];
            }
            if (tid < 64) sm.vmraw[0][tid] = vmp[kb + tid];
            __syncthreads();

            float sc[8][4];
            #pragma unroll
            for (int ri=0;ri<2;ri++){
                float mx = -1e30f;
                #pragma unroll
                for (int nj=0;nj<8;nj++){
                    #pragma unroll
                    for (int i=0;i<2;i++){
                        int kc = nj*8 + c0 + i;
                        float vm = sm.vmraw[0][kc];
                        float sv = -(1.0f - vm)*1e9f - 1e9f;   // -1e9 or -2e9
                        sc[nj][ri*2+i] = sv;
                        mx = fmaxf(mx, sv);
                    }
                }
                // no cross-lane max needed (values in {-1e9,-2e9}), but keep exact path:
                mx = fmaxf(mx, __shfl_xor_sync(0xffffffffu, mx, 1));
                mx = fmaxf(mx, __shfl_xor_sync(0xffffffffu, mx, 2));
                float mnew = fmaxf(m_r[ri], mx);
                float alpha = __expf(m_r[ri] - mnew);
                float rowsum = 0.f;
                #pragma unroll
                for (int nj=0;nj<8;nj++){
                    #pragma unroll
                    for (int i=0;i<2;i++){
                        float p = __expf(sc[nj][ri*2+i] - mnew);
                        sc[nj][ri*2+i] = p;
                        rowsum += p;
                    }
                }
                rowsum += __shfl_xor_sync(0xffffffffu, rowsum, 1);
                rowsum += __shfl_xor_sync(0xffffffffu, rowsum, 2);
                l_r[ri] = l_r[ri]*alpha + rowsum;
                m_r[ri] = mnew;
                #pragma unroll
                for (int dj=0;dj<8;dj++){
                    o[dj][ri*2+0] *= alpha;
                    o[dj][ri*2+1] *= alpha;
                }
            }

            // P is exactly {0,1} here -> P_lo == 0: 2-term PV
            uint32_t pah[4][4];
            #pragma unroll
            for (int kk2=0;kk2<4;kk2++){
                int e = kk2*2;
                pah[kk2][0] = h2u(__floats2half2_rn(sc[e][0],   sc[e][1]));
                pah[kk2][1] = h2u(__floats2half2_rn(sc[e][2],   sc[e][3]));
                pah[kk2][2] = h2u(__floats2half2_rn(sc[e+1][0], sc[e+1][1]));
                pah[kk2][3] = h2u(__floats2half2_rn(sc[e+1][2], sc[e+1][3]));
            }
            #pragma unroll
            for (int kk2=0;kk2<4;kk2++){
                uint32_t vh[8][2], vl[8][2];
                #pragma unroll
                for (int dj2=0;dj2<4;dj2++){
                    uint32_t t0,t1,t2,t3;
                    int ar = kk2*16 + (lane & 15);
                    int ac = dj2*16 + ((lane >> 4) << 3);
                    ldsm4t(t0,t1,t2,t3, s2u(&sm.Vh[0][ar][ac]));
                    vh[dj2*2][0]=t0; vh[dj2*2][1]=t1; vh[dj2*2+1][0]=t2; vh[dj2*2+1][1]=t3;
                    ldsm4t(t0,t1,t2,t3, s2u(&sm.Vl[0][ar][ac]));
                    vl[dj2*2][0]=t0; vl[dj2*2][1]=t1; vl[dj2*2+1][0]=t2; vl[dj2*2+1][1]=t3;
                }
                #pragma unroll
                for (int dj=0;dj<8;dj++){
                    mma16816(o[dj], pah[kk2], vh[dj][0], vh[dj][1]);
                    mma16816(o[dj], pah[kk2], vl[dj][0], vl[dj][1]);
                }
            }
        }
    }

    // ---- finalize: divide by l, apply q_mask, write [B,S,H*DV] fp32 ----
    #pragma unroll
    for (int ri=0;ri<2;ri++){
        int qrow = qrow0 + ri*8;
        float qm = q_mask[b*SS + qrow];
        float inv = qm / l_r[ri];
        #pragma unroll
        for (int dj=0;dj<8;dj++){
            float2 v2;
            v2.x = o[dj][ri*2+0] * inv;
            v2.y = o[dj][ri*2+1] * inv;
            *(float2*)&out[(size_t)(b*SS + qrow)*(HH*DHV) + h*DHV + dj*8 + c0] = v2;
        }
    }
}

// ---------------- launch ----------------
extern "C" void kernel_launch(void* const* d_in, const int* in_sizes, int n_in,
                              void* d_out, int out_size){
    const float* q      = (const float*)d_in[0];
    const float* k      = (const float*)d_in[1];
    const float* v      = (const float*)d_in[2];
    const float* v_mask = (const float*)d_in[3];
    const float* q_mask = (const float*)d_in[4];
    const float* Wq     = (const float*)d_in[5];
    const float* Wk     = (const float*)d_in[6];
    const float* Wv     = (const float*)d_in[7];
    float* out = (float*)d_out;

    cudaFuncSetAttribute(proj_gemm,  cudaFuncAttributeMaxDynamicSharedMemorySize, (int)sizeof(ProjSmem));
    cudaFuncSetAttribute(attn_kernel, cudaFuncAttributeMaxDynamicSharedMemorySize, (int)sizeof(AttnSmem));

    int n4x = BB*SS*DD/4;   // 2,097,152
    int n4w = DD*NN/4;      //   262,144
    cvtX<<<(3*n4x+255)/256, 256>>>((const float4*)q, (const float4*)k, (const float4*)v);
    cvtW<<<(3*n4w+255)/256, 256>>>((const float4*)Wq, (const float4*)Wk, (const float4*)Wv);

    dim3 ggrid(NN/128, (BB*SS)/128);   // (8, 64)
    proj_gemm<<<ggrid, 256, sizeof(ProjSmem)>>>(0);
    proj_gemm<<<ggrid, 256, sizeof(ProjSmem)>>>(1);
    proj_gemm<<<ggrid, 256, sizeof(ProjSmem)>>>(2);

    attn_kernel<<<dim3(SS/64, HH, BB), 128, sizeof(AttnSmem)>>>(v_mask, q_mask, out);
}

// round 6
// speedup vs baseline: 1.4816x; 1.1108x over previous
#include <cuda_runtime.h>
#include <cuda_fp16.h>
#include <cstdint>

#define BB 4
#define SS 2048
#define DD 1024
#define HH 16
#define DHK 64
#define DHV 64
#define NN (HH*DHK)   // 1024

// ---------------- scratch (no allocations allowed) ----------------
__device__ __half g_qh[BB*SS*DD];  __device__ __half g_ql[BB*SS*DD];
__device__ __half g_kh[BB*SS*DD];  __device__ __half g_kl[BB*SS*DD];
__device__ __half g_vh[BB*SS*DD];  __device__ __half g_vl[BB*SS*DD];
__device__ __half g_Wqh[DD*NN];    __device__ __half g_Wql[DD*NN];
__device__ __half g_Wkh[DD*NN];    __device__ __half g_Wkl[DD*NN];
__device__ __half g_Wvh[DD*NN];    __device__ __half g_Wvl[DD*NN];
__device__ __half g_Qh[BB*HH*SS*DHK];  __device__ __half g_Ql[BB*HH*SS*DHK];
__device__ __half g_Kh[BB*HH*SS*DHK];  __device__ __half g_Kl[BB*HH*SS*DHK];
__device__ __half g_Vh[BB*HH*SS*DHV];  __device__ __half g_Vl[BB*HH*SS*DHV];

// ---------------- helpers ----------------
__device__ __forceinline__ uint32_t s2u(const void* p){
    return (uint32_t)__cvta_generic_to_shared(p);
}
__device__ __forceinline__ void ldsm4(uint32_t& r0,uint32_t& r1,uint32_t& r2,uint32_t& r3, uint32_t a){
    asm volatile("ldmatrix.sync.aligned.m8n8.x4.shared.b16 {%0,%1,%2,%3}, [%4];"
        : "=r"(r0),"=r"(r1),"=r"(r2),"=r"(r3) : "r"(a));
}
__device__ __forceinline__ void ldsm4t(uint32_t& r0,uint32_t& r1,uint32_t& r2,uint32_t& r3, uint32_t a){
    asm volatile("ldmatrix.sync.aligned.m8n8.x4.trans.shared.b16 {%0,%1,%2,%3}, [%4];"
        : "=r"(r0),"=r"(r1),"=r"(r2),"=r"(r3) : "r"(a));
}
__device__ __forceinline__ void mma16816(float* c, const uint32_t* a, uint32_t b0, uint32_t b1){
    asm volatile("mma.sync.aligned.m16n8k16.row.col.f32.f16.f16.f32 "
        "{%0,%1,%2,%3}, {%4,%5,%6,%7}, {%8,%9}, {%0,%1,%2,%3};"
        : "+f"(c[0]),"+f"(c[1]),"+f"(c[2]),"+f"(c[3])
        : "r"(a[0]),"r"(a[1]),"r"(a[2]),"r"(a[3]),"r"(b0),"r"(b1));
}
__device__ __forceinline__ void cpasync16(uint32_t s, const void* g){
    asm volatile("cp.async.ca.shared.global [%0], [%1], 16;" :: "r"(s), "l"(g));
}
__device__ __forceinline__ void cpasync4(uint32_t s, const void* g){
    asm volatile("cp.async.ca.shared.global [%0], [%1], 4;" :: "r"(s), "l"(g));
}
#define CP_COMMIT() asm volatile("cp.async.commit_group;")
#define CP_WAIT0()  asm volatile("cp.async.wait_group 0;")
__device__ __forceinline__ uint32_t h2u(__half2 h){
    return *reinterpret_cast<uint32_t*>(&h);
}
__device__ __forceinline__ void split1(float x, __half& h, __half& l){
    h = __float2half_rn(x);
    l = __float2half_rn(x - __half2float(h));
}

// ---------------- fp32 -> fp16 hi/lo split (merged launches) ----------------
__global__ void cvtX(const float4* __restrict__ q, const float4* __restrict__ k,
                     const float4* __restrict__ v){
    const int n4 = BB*SS*DD/4;
    int i = blockIdx.x*blockDim.x + threadIdx.x;
    const float4* src; __half *dh, *dl; int j;
    if (i < n4){ src=q; dh=g_qh; dl=g_ql; j=i; }
    else if (i < 2*n4){ src=k; dh=g_kh; dl=g_kl; j=i-n4; }
    else if (i < 3*n4){ src=v; dh=g_vh; dl=g_vl; j=i-2*n4; }
    else return;
    float4 f = src[j];
    __half h0,l0,h1,l1,h2,l2,h3,l3;
    split1(f.x,h0,l0); split1(f.y,h1,l1); split1(f.z,h2,l2); split1(f.w,h3,l3);
    ((__half2*)dh)[2*j+0] = __halves2half2(h0,h1);
    ((__half2*)dh)[2*j+1] = __halves2half2(h2,h3);
    ((__half2*)dl)[2*j+0] = __halves2half2(l0,l1);
    ((__half2*)dl)[2*j+1] = __halves2half2(l2,l3);
}
__global__ void cvtW(const float4* __restrict__ wq, const float4* __restrict__ wk,
                     const float4* __restrict__ wv){
    const int n4 = DD*NN/4;
    int i = blockIdx.x*blockDim.x + threadIdx.x;
    const float4* src; __half *dh, *dl; int j;
    if (i < n4){ src=wq; dh=g_Wqh; dl=g_Wql; j=i; }
    else if (i < 2*n4){ src=wk; dh=g_Wkh; dl=g_Wkl; j=i-n4; }
    else if (i < 3*n4){ src=wv; dh=g_Wvh; dl=g_Wvl; j=i-2*n4; }
    else return;
    float4 f = src[j];
    __half h0,l0,h1,l1,h2,l2,h3,l3;
    split1(f.x,h0,l0); split1(f.y,h1,l1); split1(f.z,h2,l2); split1(f.w,h3,l3);
    ((__half2*)dh)[2*j+0] = __halves2half2(h0,h1);
    ((__half2*)dh)[2*j+1] = __halves2half2(h2,h3);
    ((__half2*)dl)[2*j+0] = __halves2half2(l0,l1);
    ((__half2*)dl)[2*j+1] = __halves2half2(l2,l3);
}

// ---------------- projection GEMM (split fp16, 3-term, BK=32, 2 CTA/SM) ----------------
#define PBK 32

struct ProjSmem {
    __half Ah[2][128][40], Al[2][128][40];
    __half Wh[2][PBK][136], Wl[2][PBK][136];
};

__global__ __launch_bounds__(256, 2) void proj_gemm(){
    int which = blockIdx.z;
    const __half *Ah_, *Al_, *Wh_, *Wl_; __half *Oh, *Ol; float scale;
    if (which==0){ Ah_=g_qh; Al_=g_ql; Wh_=g_Wqh; Wl_=g_Wql; Oh=g_Qh; Ol=g_Ql; scale=0.125f; }
    else if (which==1){ Ah_=g_kh; Al_=g_kl; Wh_=g_Wkh; Wl_=g_Wkl; Oh=g_Kh; Ol=g_Kl; scale=1.f; }
    else { Ah_=g_vh; Al_=g_vl; Wh_=g_Wvh; Wl_=g_Wvl; Oh=g_Vh; Ol=g_Vl; scale=1.f; }

    extern __shared__ char smem_raw[];
    ProjSmem& sm = *reinterpret_cast<ProjSmem*>(smem_raw);

    int tid = threadIdx.x;
    int warp = tid >> 5, lane = tid & 31;
    int wm = warp >> 1, wn = warp & 1;     // 4 x 2 warp grid
    int bm0 = blockIdx.y * 128;
    int bn0 = blockIdx.x * 128;

    float acc[2][8][4];
    #pragma unroll
    for (int mi=0;mi<2;mi++)
        #pragma unroll
        for (int nj=0;nj<8;nj++)
            #pragma unroll
            for (int t=0;t<4;t++) acc[mi][nj][t] = 0.f;

    const int KT = DD / PBK;  // 32

    // prologue: stage tile 0
    #pragma unroll
    for (int j=0;j<2;j++){
        int idx = tid + j*256;
        int r = idx >> 2, cc = (idx & 3) * 8;
        cpasync16(s2u(&sm.Ah[0][r][cc]), Ah_ + (size_t)(bm0+r)*DD + cc);
        cpasync16(s2u(&sm.Al[0][r][cc]), Al_ + (size_t)(bm0+r)*DD + cc);
        int wr = idx >> 4, wc = (idx & 15) * 8;
        cpasync16(s2u(&sm.Wh[0][wr][wc]), Wh_ + (size_t)wr*NN + bn0 + wc);
        cpasync16(s2u(&sm.Wl[0][wr][wc]), Wl_ + (size_t)wr*NN + bn0 + wc);
    }
    CP_COMMIT(); CP_WAIT0();
    __syncthreads();

    for (int kt = 0; kt < KT; kt++){
        int buf = kt & 1;
        if (kt + 1 < KT){
            int k0 = (kt+1) * PBK;
            int nb = buf ^ 1;
            #pragma unroll
            for (int j=0;j<2;j++){
                int idx = tid + j*256;
                int r = idx >> 2, cc = (idx & 3) * 8;
                cpasync16(s2u(&sm.Ah[nb][r][cc]), Ah_ + (size_t)(bm0+r)*DD + k0 + cc);
                cpasync16(s2u(&sm.Al[nb][r][cc]), Al_ + (size_t)(bm0+r)*DD + k0 + cc);
                int wr = idx >> 4, wc = (idx & 15) * 8;
                cpasync16(s2u(&sm.Wh[nb][wr][wc]), Wh_ + (size_t)(k0+wr)*NN + bn0 + wc);
                cpasync16(s2u(&sm.Wl[nb][wr][wc]), Wl_ + (size_t)(k0+wr)*NN + bn0 + wc);
            }
            CP_COMMIT();
        }

        #pragma unroll
        for (int kk=0; kk<2; kk++){
            int k0c = kk*16;
            uint32_t ah[2][4], al[2][4];
            #pragma unroll
            for (int mi=0; mi<2; mi++){
                ldsm4(ah[mi][0],ah[mi][1],ah[mi][2],ah[mi][3],
                    s2u(&sm.Ah[buf][wm*32 + mi*16 + (lane & 15)][k0c + ((lane >> 4) << 3)]));
                ldsm4(al[mi][0],al[mi][1],al[mi][2],al[mi][3],
                    s2u(&sm.Al[buf][wm*32 + mi*16 + (lane & 15)][k0c + ((lane >> 4) << 3)]));
            }
            uint32_t bh[8][2], bl[8][2];
            #pragma unroll
            for (int nj2=0; nj2<4; nj2++){
                uint32_t t0,t1,t2,t3;
                ldsm4t(t0,t1,t2,t3,
                    s2u(&sm.Wh[buf][k0c + (lane & 15)][wn*64 + nj2*16 + ((lane >> 4) << 3)]));
                bh[nj2*2][0]=t0; bh[nj2*2][1]=t1; bh[nj2*2+1][0]=t2; bh[nj2*2+1][1]=t3;
                ldsm4t(t0,t1,t2,t3,
                    s2u(&sm.Wl[buf][k0c + (lane & 15)][wn*64 + nj2*16 + ((lane >> 4) << 3)]));
                bl[nj2*2][0]=t0; bl[nj2*2][1]=t1; bl[nj2*2+1][0]=t2; bl[nj2*2+1][1]=t3;
            }
            #pragma unroll
            for (int mi=0;mi<2;mi++)
                #pragma unroll
                for (int nj=0;nj<8;nj++){
                    mma16816(acc[mi][nj], ah[mi], bh[nj][0], bh[nj][1]);
                    mma16816(acc[mi][nj], ah[mi], bl[nj][0], bl[nj][1]);
                    mma16816(acc[mi][nj], al[mi], bh[nj][0], bh[nj][1]);
                }
        }

        if (kt + 1 < KT) CP_WAIT0();
        __syncthreads();
    }

    // epilogue: split + scatter into [B,H,S,64]
    int r0 = lane >> 2, c0 = (lane & 3) * 2;
    #pragma unroll
    for (int mi=0;mi<2;mi++){
        #pragma unroll
        for (int ri=0;ri<2;ri++){
            int m = bm0 + wm*32 + mi*16 + r0 + ri*8;
            int bbi = m >> 11, s = m & (SS-1);
            #pragma unroll
            for (int nj=0;nj<8;nj++){
                int n = bn0 + wn*64 + nj*8 + c0;
                int h = n >> 6, c = n & 63;
                float x0 = acc[mi][nj][ri*2+0]*scale;
                float x1 = acc[mi][nj][ri*2+1]*scale;
                __half h0,l0,h1,l1;
                split1(x0,h0,l0); split1(x1,h1,l1);
                size_t base = (((size_t)(bbi*HH + h)*SS + s) << 6) + c;
                *(__half2*)&Oh[base] = __halves2half2(h0,h1);
                *(__half2*)&Ol[base] = __halves2half2(l0,l1);
            }
        }
    }
}

// ---------------- flash attention ----------------
// 128 q-rows per CTA, 8 warps (16 rows each); 64-key double-buffered blocks.
struct AttnSmem {
    __half Qh[128][72], Ql[128][72];
    __half Kh[2][64][72], Kl[2][64][72];
    __half Vh[2][64][72], Vl[2][64][72];
    float  vmraw[2][64];
};

__global__ __launch_bounds__(256) void attn_kernel(const float* __restrict__ v_mask,
                                                   const float* __restrict__ q_mask,
                                                   float* __restrict__ out){
    int qt = blockIdx.x, h = blockIdx.y, b = blockIdx.z;
    int tid = threadIdx.x, warp = tid >> 5, lane = tid & 31;
    int qb = qt * 128;

    extern __shared__ char smem_raw[];
    AttnSmem& sm = *reinterpret_cast<AttnSmem*>(smem_raw);

    size_t hb = (size_t)(b*HH + h) * SS;
    const __half* Qph = g_Qh + hb*DHK;  const __half* Qpl = g_Ql + hb*DHK;
    const __half* Kph = g_Kh + hb*DHK;  const __half* Kpl = g_Kl + hb*DHK;
    const __half* Vph = g_Vh + hb*DHV;  const __half* Vpl = g_Vl + hb*DHV;
    const float*  vmp = v_mask + b*SS;

    // prologue: async-stage K/V block 0, plain-stage Q
    for (int c = tid; c < 512; c += 256){
        int r = c >> 3, cc = (c & 7) * 8;
        size_t off = (size_t)r*DHK + cc;
        cpasync16(s2u(&sm.Kh[0][r][cc]), Kph + off);
        cpasync16(s2u(&sm.Kl[0][r][cc]), Kpl + off);
        cpasync16(s2u(&sm.Vh[0][r][cc]), Vph + off);
        cpasync16(s2u(&sm.Vl[0][r][cc]), Vpl + off);
    }
    if (tid < 64) cpasync4(s2u(&sm.vmraw[0][tid]), vmp + tid);
    CP_COMMIT();
    for (int c = tid; c < 1024; c += 256){
        int r = c >> 3, cc = (c & 7) * 8;
        *(uint4*)&sm.Qh[r][cc] = *(const uint4*)&Qph[(size_t)(qb + r)*DHK + cc];
        *(uint4*)&sm.Ql[r][cc] = *(const uint4*)&Qpl[(size_t)(qb + r)*DHK + cc];
    }
    CP_WAIT0();
    __syncthreads();

    uint32_t qh[4][4], ql[4][4];
    #pragma unroll
    for (int kk=0; kk<4; kk++){
        ldsm4(qh[kk][0],qh[kk][1],qh[kk][2],qh[kk][3],
            s2u(&sm.Qh[warp*16 + (lane & 15)][kk*16 + ((lane >> 4) << 3)]));
        ldsm4(ql[kk][0],ql[kk][1],ql[kk][2],ql[kk][3],
            s2u(&sm.Ql[warp*16 + (lane & 15)][kk*16 + ((lane >> 4) << 3)]));
    }

    float m_r[2] = {-1e30f, -1e30f};
    float l_r[2] = {0.f, 0.f};
    float o[8][4];
    #pragma unroll
    for (int dj=0;dj<8;dj++)
        #pragma unroll
        for (int t=0;t<4;t++) o[dj][t] = 0.f;

    int r0 = lane >> 2, c0 = (lane & 3) * 2;
    int qrow0 = qb + warp*16 + r0;
    int g = lane >> 3;

    const int nvis = 2*qt + 2;  // 64-key blocks covering keys <= qb+127

    for (int ib = 0; ib < nvis; ib++){
        int buf = ib & 1;
        int kb = ib * 64;
        bool more = (ib + 1 < nvis);
        if (more){
            int nb = buf ^ 1;
            int kb2 = kb + 64;
            for (int c = tid; c < 512; c += 256){
                int r = c >> 3, cc = (c & 7) * 8;
                size_t off = (size_t)(kb2 + r)*DHK + cc;
                cpasync16(s2u(&sm.Kh[nb][r][cc]), Kph + off);
                cpasync16(s2u(&sm.Kl[nb][r][cc]), Kpl + off);
                cpasync16(s2u(&sm.Vh[nb][r][cc]), Vph + off);
                cpasync16(s2u(&sm.Vl[nb][r][cc]), Vpl + off);
            }
            if (tid < 64) cpasync4(s2u(&sm.vmraw[nb][tid]), vmp + kb2 + tid);
            CP_COMMIT();
        }

        // ---- scores: S = Q K^T (3-term split) ----
        float sc[8][4];
        #pragma unroll
        for (int nj=0;nj<8;nj++)
            #pragma unroll
            for (int t=0;t<4;t++) sc[nj][t] = 0.f;

        #pragma unroll
        for (int kk=0;kk<4;kk++){
            uint32_t bh[8][2], bl[8][2];
            #pragma unroll
            for (int nj2=0;nj2<4;nj2++){
                uint32_t t0,t1,t2,t3;
                int ar = nj2*16 + ((g>>1)<<3) + (lane & 7);
                int ac = kk*16 + ((g & 1)<<3);
                ldsm4(t0,t1,t2,t3, s2u(&sm.Kh[buf][ar][ac]));
                bh[nj2*2][0]=t0; bh[nj2*2][1]=t1; bh[nj2*2+1][0]=t2; bh[nj2*2+1][1]=t3;
                ldsm4(t0,t1,t2,t3, s2u(&sm.Kl[buf][ar][ac]));
                bl[nj2*2][0]=t0; bl[nj2*2][1]=t1; bl[nj2*2+1][0]=t2; bl[nj2*2+1][1]=t3;
            }
            #pragma unroll
            for (int nj=0;nj<8;nj++){
                mma16816(sc[nj], qh[kk], bh[nj][0], bh[nj][1]);
                mma16816(sc[nj], qh[kk], bl[nj][0], bl[nj][1]);
                mma16816(sc[nj], ql[kk], bh[nj][0], bh[nj][1]);
            }
        }

        // ---- mask + online softmax ----
        // causal needed only when block reaches this warp's rows
        bool diag = (kb + 63 > qb + warp*16);
        #pragma unroll
        for (int ri=0;ri<2;ri++){
            int qrow = qrow0 + ri*8;
            float mx = -1e30f;
            #pragma unroll
            for (int nj=0;nj<8;nj++){
                #pragma unroll
                for (int i=0;i<2;i++){
                    int kc = nj*8 + c0 + i;
                    float vm = sm.vmraw[buf][kc];
                    float sv = sc[nj][ri*2+i] - (1.0f - vm)*1e9f;
                    if (diag && (kb + kc > qrow)) sv -= 1e9f;
                    sc[nj][ri*2+i] = sv;
                    mx = fmaxf(mx, sv);
                }
            }
            mx = fmaxf(mx, __shfl_xor_sync(0xffffffffu, mx, 1));
            mx = fmaxf(mx, __shfl_xor_sync(0xffffffffu, mx, 2));
            float mnew = fmaxf(m_r[ri], mx);
            float alpha = __expf(m_r[ri] - mnew);
            float rowsum = 0.f;
            #pragma unroll
            for (int nj=0;nj<8;nj++){
                #pragma unroll
                for (int i=0;i<2;i++){
                    float p = __expf(sc[nj][ri*2+i] - mnew);
                    sc[nj][ri*2+i] = p;
                    rowsum += p;
                }
            }
            rowsum += __shfl_xor_sync(0xffffffffu, rowsum, 1);
            rowsum += __shfl_xor_sync(0xffffffffu, rowsum, 2);
            l_r[ri] = l_r[ri]*alpha + rowsum;
            m_r[ri] = mnew;
            #pragma unroll
            for (int dj=0;dj<8;dj++){
                o[dj][ri*2+0] *= alpha;
                o[dj][ri*2+1] *= alpha;
            }
        }

        // ---- P split to hi/lo fp16 fragments ----
        uint32_t pah[4][4], pal[4][4];
        #pragma unroll
        for (int kk2=0;kk2<4;kk2++){
            int e = kk2*2;
            __half h0,l0,h1,l1;
            split1(sc[e][0],h0,l0); split1(sc[e][1],h1,l1);
            pah[kk2][0] = h2u(__halves2half2(h0,h1)); pal[kk2][0] = h2u(__halves2half2(l0,l1));
            split1(sc[e][2],h0,l0); split1(sc[e][3],h1,l1);
            pah[kk2][1] = h2u(__halves2half2(h0,h1)); pal[kk2][1] = h2u(__halves2half2(l0,l1));
            split1(sc[e+1][0],h0,l0); split1(sc[e+1][1],h1,l1);
            pah[kk2][2] = h2u(__halves2half2(h0,h1)); pal[kk2][2] = h2u(__halves2half2(l0,l1));
            split1(sc[e+1][2],h0,l0); split1(sc[e+1][3],h1,l1);
            pah[kk2][3] = h2u(__halves2half2(h0,h1)); pal[kk2][3] = h2u(__halves2half2(l0,l1));
        }

        // ---- O += P V (3-term) ----
        #pragma unroll
        for (int kk2=0;kk2<4;kk2++){
            uint32_t vh[8][2], vl[8][2];
            #pragma unroll
            for (int dj2=0;dj2<4;dj2++){
                uint32_t t0,t1,t2,t3;
                int ar = kk2*16 + (lane & 15);
                int ac = dj2*16 + ((lane >> 4) << 3);
                ldsm4t(t0,t1,t2,t3, s2u(&sm.Vh[buf][ar][ac]));
                vh[dj2*2][0]=t0; vh[dj2*2][1]=t1; vh[dj2*2+1][0]=t2; vh[dj2*2+1][1]=t3;
                ldsm4t(t0,t1,t2,t3, s2u(&sm.Vl[buf][ar][ac]));
                vl[dj2*2][0]=t0; vl[dj2*2][1]=t1; vl[dj2*2+1][0]=t2; vl[dj2*2+1][1]=t3;
            }
            #pragma unroll
            for (int dj=0;dj<8;dj++){
                mma16816(o[dj], pah[kk2], vh[dj][0], vh[dj][1]);
                mma16816(o[dj], pah[kk2], vl[dj][0], vl[dj][1]);
                mma16816(o[dj], pal[kk2], vh[dj][0], vh[dj][1]);
            }
        }

        if (more) CP_WAIT0();
        __syncthreads();
    }

    // ---- future phase: rows whose entire visible range was v_masked ----
    int need = __syncthreads_or((m_r[0] < -5e8f) || (m_r[1] < -5e8f));
    if (need){
        for (int kb = qb + 128; kb < SS; kb += 64){
            __syncthreads();
            for (int c = tid; c < 512; c += 256){
                int r = c >> 3, cc = (c & 7) * 8;
                size_t off = (size_t)(kb + r)*DHV + cc;
                *(uint4*)&sm.Vh[0][r][cc] = *(const uint4*)&Vph[off];
                *(uint4*)&sm.Vl[0][r][cc] = *(const uint4*)&Vpl[off];
            }
            if (tid < 64) sm.vmraw[0][tid] = vmp[kb + tid];
            __syncthreads();

            float sc[8][4];
            #pragma unroll
            for (int ri=0;ri<2;ri++){
                float mx = -1e30f;
                #pragma unroll
                for (int nj=0;nj<8;nj++){
                    #pragma unroll
                    for (int i=0;i<2;i++){
                        int kc = nj*8 + c0 + i;
                        float vm = sm.vmraw[0][kc];
                        float sv = -(1.0f - vm)*1e9f - 1e9f;   // -1e9 or -2e9
                        sc[nj][ri*2+i] = sv;
                        mx = fmaxf(mx, sv);
                    }
                }
                mx = fmaxf(mx, __shfl_xor_sync(0xffffffffu, mx, 1));
                mx = fmaxf(mx, __shfl_xor_sync(0xffffffffu, mx, 2));
                float mnew = fmaxf(m_r[ri], mx);
                float alpha = __expf(m_r[ri] - mnew);
                float rowsum = 0.f;
                #pragma unroll
                for (int nj=0;nj<8;nj++){
                    #pragma unroll
                    for (int i=0;i<2;i++){
                        float p = __expf(sc[nj][ri*2+i] - mnew);
                        sc[nj][ri*2+i] = p;
                        rowsum += p;
                    }
                }
                rowsum += __shfl_xor_sync(0xffffffffu, rowsum, 1);
                rowsum += __shfl_xor_sync(0xffffffffu, rowsum, 2);
                l_r[ri] = l_r[ri]*alpha + rowsum;
                m_r[ri] = mnew;
                #pragma unroll
                for (int dj=0;dj<8;dj++){
                    o[dj][ri*2+0] *= alpha;
                    o[dj][ri*2+1] *= alpha;
                }
            }

            // P exactly {0,1} -> P_lo == 0: 2-term PV
            uint32_t pah[4][4];
            #pragma unroll
            for (int kk2=0;kk2<4;kk2++){
                int e = kk2*2;
                pah[kk2][0] = h2u(__floats2half2_rn(sc[e][0],   sc[e][1]));
                pah[kk2][1] = h2u(__floats2half2_rn(sc[e][2],   sc[e][3]));
                pah[kk2][2] = h2u(__floats2half2_rn(sc[e+1][0], sc[e+1][1]));
                pah[kk2][3] = h2u(__floats2half2_rn(sc[e+1][2], sc[e+1][3]));
            }
            #pragma unroll
            for (int kk2=0;kk2<4;kk2++){
                uint32_t vh[8][2], vl[8][2];
                #pragma unroll
                for (int dj2=0;dj2<4;dj2++){
                    uint32_t t0,t1,t2,t3;
                    int ar = kk2*16 + (lane & 15);
                    int ac = dj2*16 + ((lane >> 4) << 3);
                    ldsm4t(t0,t1,t2,t3, s2u(&sm.Vh[0][ar][ac]));
                    vh[dj2*2][0]=t0; vh[dj2*2][1]=t1; vh[dj2*2+1][0]=t2; vh[dj2*2+1][1]=t3;
                    ldsm4t(t0,t1,t2,t3, s2u(&sm.Vl[0][ar][ac]));
                    vl[dj2*2][0]=t0; vl[dj2*2][1]=t1; vl[dj2*2+1][0]=t2; vl[dj2*2+1][1]=t3;
                }
                #pragma unroll
                for (int dj=0;dj<8;dj++){
                    mma16816(o[dj], pah[kk2], vh[dj][0], vh[dj][1]);
                    mma16816(o[dj], pah[kk2], vl[dj][0], vl[dj][1]);
                }
            }
        }
    }

    // ---- finalize: divide by l, apply q_mask, write [B,S,H*DV] fp32 ----
    #pragma unroll
    for (int ri=0;ri<2;ri++){
        int qrow = qrow0 + ri*8;
        float qm = q_mask[b*SS + qrow];
        float inv = qm / l_r[ri];
        #pragma unroll
        for (int dj=0;dj<8;dj++){
            float2 v2;
            v2.x = o[dj][ri*2+0] * inv;
            v2.y = o[dj][ri*2+1] * inv;
            *(float2*)&out[(size_t)(b*SS + qrow)*(HH*DHV) + h*DHV + dj*8 + c0] = v2;
        }
    }
}

// ---------------- launch ----------------
extern "C" void kernel_launch(void* const* d_in, const int* in_sizes, int n_in,
                              void* d_out, int out_size){
    const float* q      = (const float*)d_in[0];
    const float* k      = (const float*)d_in[1];
    const float* v      = (const float*)d_in[2];
    const float* v_mask = (const float*)d_in[3];
    const float* q_mask = (const float*)d_in[4];
    const float* Wq     = (const float*)d_in[5];
    const float* Wk     = (const float*)d_in[6];
    const float* Wv     = (const float*)d_in[7];
    float* out = (float*)d_out;

    cudaFuncSetAttribute(proj_gemm,  cudaFuncAttributeMaxDynamicSharedMemorySize, (int)sizeof(ProjSmem));
    cudaFuncSetAttribute(attn_kernel, cudaFuncAttributeMaxDynamicSharedMemorySize, (int)sizeof(AttnSmem));

    int n4x = BB*SS*DD/4;
    int n4w = DD*NN/4;
    cvtX<<<(3*n4x+255)/256, 256>>>((const float4*)q, (const float4*)k, (const float4*)v);
    cvtW<<<(3*n4w+255)/256, 256>>>((const float4*)Wq, (const float4*)Wk, (const float4*)Wv);

    dim3 ggrid(NN/128, (BB*SS)/128, 3);   // (8, 64, 3)
    proj_gemm<<<ggrid, 256, sizeof(ProjSmem)>>>();

    attn_kernel<<<dim3(SS/128, HH, BB), 256, sizeof(AttnSmem)>>>(v_mask, q_mask, out);
}